// round 3
// baseline (speedup 1.0000x reference)
#include <cuda_runtime.h>
#include <mma.h>

using namespace nvcuda;

#define HID    1024
#define NHEADS 16
#define HDIM   64
#define BATCH  8
#define SEQ    1024
#define MROWS  (BATCH*SEQ)        // 8192
#define BHS    (BATCH*NHEADS*SEQ) // 131072

// Scratch (device globals — no allocation allowed)
__device__ float g_Q[MROWS*HID];
__device__ float g_K[MROWS*HID];
__device__ float g_V[MROWS*HID];
__device__ float g_O[MROWS*HID];
__device__ float g_rmax[BHS];
__device__ float g_rinv[BHS];

#define TBM 128
#define TBN 128
#define TBK 32
#define LDT 36    // padded smem leading dim (floats)

// ---------------------------------------------------------------------------
// NT GEMM: C[M,1024] = A[M,1024] @ W[1024,1024]^T   (tf32 tensor cores)
// ---------------------------------------------------------------------------
__global__ __launch_bounds__(256)
void proj_kernel(const float* __restrict__ A, const float* __restrict__ W,
                 float* __restrict__ C)
{
    __shared__ float As[TBM*LDT];
    __shared__ float Bs[TBN*LDT];

    const int tid  = threadIdx.x;
    const int warp = tid >> 5;
    const int wm   = warp & 3;   // 4 warps along M (32 rows each)
    const int wn   = warp >> 2;  // 2 warps along N (64 cols each)
    const int m0   = blockIdx.y * TBM;
    const int n0   = blockIdx.x * TBN;

    wmma::fragment<wmma::accumulator,16,16,8,float> acc[2][4];
    #pragma unroll
    for (int mi=0; mi<2; mi++)
        #pragma unroll
        for (int ni=0; ni<4; ni++)
            wmma::fill_fragment(acc[mi][ni], 0.0f);

    const int lrow = tid >> 3;        // 0..31
    const int lcol = (tid & 7) * 4;   // 0..28

    float4 ra[4], rb[4];
    #pragma unroll
    for (int i=0;i<4;i++){
        ra[i] = *(const float4*)(A + (size_t)(m0 + lrow + i*32)*HID + lcol);
        rb[i] = *(const float4*)(W + (size_t)(n0 + lrow + i*32)*HID + lcol);
    }

    const int NKT = HID / TBK;  // 32
    for (int kt=0; kt<NKT; kt++){
        #pragma unroll
        for (int i=0;i<4;i++){
            *(float4*)(As + (lrow+i*32)*LDT + lcol) = ra[i];
            *(float4*)(Bs + (lrow+i*32)*LDT + lcol) = rb[i];
        }
        __syncthreads();
        if (kt+1 < NKT){
            const int k0 = (kt+1)*TBK;
            #pragma unroll
            for (int i=0;i<4;i++){
                ra[i] = *(const float4*)(A + (size_t)(m0 + lrow + i*32)*HID + k0 + lcol);
                rb[i] = *(const float4*)(W + (size_t)(n0 + lrow + i*32)*HID + k0 + lcol);
            }
        }
        #pragma unroll
        for (int kk=0; kk<TBK; kk+=8){
            wmma::fragment<wmma::matrix_a,16,16,8,wmma::precision::tf32,wmma::row_major> af[2];
            wmma::fragment<wmma::matrix_b,16,16,8,wmma::precision::tf32,wmma::col_major> bf[4];
            #pragma unroll
            for (int mi=0;mi<2;mi++){
                wmma::load_matrix_sync(af[mi], As + (wm*32+mi*16)*LDT + kk, LDT);
                #pragma unroll
                for (int t=0;t<af[mi].num_elements;t++)
                    af[mi].x[t] = wmma::__float_to_tf32(af[mi].x[t]);
            }
            #pragma unroll
            for (int ni=0;ni<4;ni++){
                wmma::load_matrix_sync(bf[ni], Bs + (wn*64+ni*16)*LDT + kk, LDT);
                #pragma unroll
                for (int t=0;t<bf[ni].num_elements;t++)
                    bf[ni].x[t] = wmma::__float_to_tf32(bf[ni].x[t]);
            }
            #pragma unroll
            for (int mi=0;mi<2;mi++)
                #pragma unroll
                for (int ni=0;ni<4;ni++)
                    wmma::mma_sync(acc[mi][ni], af[mi], bf[ni], acc[mi][ni]);
        }
        __syncthreads();
    }

    #pragma unroll
    for (int mi=0;mi<2;mi++)
        #pragma unroll
        for (int ni=0;ni<4;ni++){
            float* dst = C + (size_t)(m0 + wm*32 + mi*16)*HID + n0 + wn*64 + ni*16;
            wmma::store_matrix_sync(dst, acc[mi][ni], HID, wmma::mem_row_major);
        }
}

// ---------------------------------------------------------------------------
// C[i] = (C[i] + bias[i % HID]) * scale
// ---------------------------------------------------------------------------
__global__ __launch_bounds__(256)
void bias_scale_kernel(float* __restrict__ C, const float* __restrict__ bias, float scale)
{
    size_t idx = ((size_t)blockIdx.x * blockDim.x + threadIdx.x) * 4;
    float4 v = *(float4*)(C + idx);
    int col = (int)(idx & (HID-1));
    float4 b = *(const float4*)(bias + col);
    v.x = (v.x + b.x) * scale;
    v.y = (v.y + b.y) * scale;
    v.z = (v.z + b.z) * scale;
    v.w = (v.w + b.w) * scale;
    *(float4*)(C + idx) = v;
}

// ---------------------------------------------------------------------------
// Energy: per (b,h): E = Qh @ Kh^T (Q already pre-scaled by 1/8). Raw E -> attn.
// ---------------------------------------------------------------------------
__global__ __launch_bounds__(256)
void energy_kernel(float* __restrict__ attn)
{
    __shared__ float As[TBM*LDT];
    __shared__ float Bs[TBN*LDT];

    const int tid  = threadIdx.x;
    const int warp = tid >> 5;
    const int wm   = warp & 3;
    const int wn   = warp >> 2;
    const int bh   = blockIdx.z;
    const int b    = bh >> 4;
    const int h    = bh & 15;
    const int m0   = blockIdx.y * TBM;
    const int n0   = blockIdx.x * TBN;

    const float* Ab = g_Q + (size_t)b*SEQ*HID + h*HDIM;
    const float* Bb = g_K + (size_t)b*SEQ*HID + h*HDIM;

    wmma::fragment<wmma::accumulator,16,16,8,float> acc[2][4];
    #pragma unroll
    for (int mi=0; mi<2; mi++)
        #pragma unroll
        for (int ni=0; ni<4; ni++)
            wmma::fill_fragment(acc[mi][ni], 0.0f);

    const int lrow = tid >> 3;
    const int lcol = (tid & 7) * 4;

    float4 ra[4], rb[4];
    #pragma unroll
    for (int i=0;i<4;i++){
        ra[i] = *(const float4*)(Ab + (size_t)(m0 + lrow + i*32)*HID + lcol);
        rb[i] = *(const float4*)(Bb + (size_t)(n0 + lrow + i*32)*HID + lcol);
    }

    const int NKT = HDIM / TBK;  // 2
    for (int kt=0; kt<NKT; kt++){
        #pragma unroll
        for (int i=0;i<4;i++){
            *(float4*)(As + (lrow+i*32)*LDT + lcol) = ra[i];
            *(float4*)(Bs + (lrow+i*32)*LDT + lcol) = rb[i];
        }
        __syncthreads();
        if (kt+1 < NKT){
            const int k0 = (kt+1)*TBK;
            #pragma unroll
            for (int i=0;i<4;i++){
                ra[i] = *(const float4*)(Ab + (size_t)(m0 + lrow + i*32)*HID + k0 + lcol);
                rb[i] = *(const float4*)(Bb + (size_t)(n0 + lrow + i*32)*HID + k0 + lcol);
            }
        }
        #pragma unroll
        for (int kk=0; kk<TBK; kk+=8){
            wmma::fragment<wmma::matrix_a,16,16,8,wmma::precision::tf32,wmma::row_major> af[2];
            wmma::fragment<wmma::matrix_b,16,16,8,wmma::precision::tf32,wmma::col_major> bf[4];
            #pragma unroll
            for (int mi=0;mi<2;mi++){
                wmma::load_matrix_sync(af[mi], As + (wm*32+mi*16)*LDT + kk, LDT);
                #pragma unroll
                for (int t=0;t<af[mi].num_elements;t++)
                    af[mi].x[t] = wmma::__float_to_tf32(af[mi].x[t]);
            }
            #pragma unroll
            for (int ni=0;ni<4;ni++){
                wmma::load_matrix_sync(bf[ni], Bs + (wn*64+ni*16)*LDT + kk, LDT);
                #pragma unroll
                for (int t=0;t<bf[ni].num_elements;t++)
                    bf[ni].x[t] = wmma::__float_to_tf32(bf[ni].x[t]);
            }
            #pragma unroll
            for (int mi=0;mi<2;mi++)
                #pragma unroll
                for (int ni=0;ni<4;ni++)
                    wmma::mma_sync(acc[mi][ni], af[mi], bf[ni], acc[mi][ni]);
        }
        __syncthreads();
    }

    float* Cb = attn + (size_t)bh*SEQ*SEQ;
    #pragma unroll
    for (int mi=0;mi<2;mi++)
        #pragma unroll
        for (int ni=0;ni<4;ni++){
            float* dst = Cb + (size_t)(m0 + wm*32 + mi*16)*SEQ + n0 + wn*64 + ni*16;
            wmma::store_matrix_sync(dst, acc[mi][ni], SEQ, wmma::mem_row_major);
        }
}

// ---------------------------------------------------------------------------
// Row stats: rowmax + 1/rowsum of exp(masked E - rowmax). One warp per row.
// ---------------------------------------------------------------------------
__global__ __launch_bounds__(256)
void stats_kernel(const float* __restrict__ attn, const int* __restrict__ mask)
{
    const int rid  = blockIdx.x * 8 + (threadIdx.x >> 5);
    const int lane = threadIdx.x & 31;
    const float* row = attn + (size_t)rid * SEQ;
    const int b = rid >> 14;                 // rid / (NHEADS*SEQ)
    const int* mrow = mask + b * SEQ;

    float v[32];
    float m = -1e30f;
    #pragma unroll
    for (int i=0;i<8;i++){
        float4 t = *(const float4*)(row + i*128 + lane*4);
        int4   mk = *(const int4*)(mrow + i*128 + lane*4);
        t.x = (mk.x == 0) ? -1e10f : t.x;
        t.y = (mk.y == 0) ? -1e10f : t.y;
        t.z = (mk.z == 0) ? -1e10f : t.z;
        t.w = (mk.w == 0) ? -1e10f : t.w;
        v[i*4+0]=t.x; v[i*4+1]=t.y; v[i*4+2]=t.z; v[i*4+3]=t.w;
        m = fmaxf(m, fmaxf(fmaxf(t.x,t.y), fmaxf(t.z,t.w)));
    }
    #pragma unroll
    for (int o=16;o;o>>=1) m = fmaxf(m, __shfl_xor_sync(0xffffffffu, m, o));
    float s = 0.0f;
    #pragma unroll
    for (int i=0;i<32;i++) s += __expf(v[i] - m);
    #pragma unroll
    for (int o=16;o;o>>=1) s += __shfl_xor_sync(0xffffffffu, s, o);
    if (lane == 0){ g_rmax[rid] = m; g_rinv[rid] = 1.0f / s; }
}

// ---------------------------------------------------------------------------
// AV: per (b,h): P = softmax(E) (written back in place to attn), O = P @ Vh.
// ---------------------------------------------------------------------------
#define AVLDP 36
#define AVLDV 68
__global__ __launch_bounds__(256)
void av_kernel(float* __restrict__ attn, const int* __restrict__ mask)
{
    __shared__ float Ps[TBM*AVLDP];   // 128 x 32 (padded)
    __shared__ float Vs[TBK*AVLDV];   // 32 x 64 (padded)

    const int tid  = threadIdx.x;
    const int warp = tid >> 5;
    const int wm   = warp & 3;    // 32 rows per warp
    const int wn   = warp >> 2;   // 32 cols per warp
    const int bh   = blockIdx.y;
    const int b    = bh >> 4;
    const int h    = bh & 15;
    const int m0   = blockIdx.x * TBM;

    float* Arow = attn + ((size_t)bh*SEQ + m0) * SEQ;
    const float* Vb = g_V + (size_t)b*SEQ*HID + h*HDIM;
    const int* maskb = mask + b*SEQ;

    const int lrow = tid >> 3;
    const int lcol = (tid & 7) * 4;
    const int vrow = tid >> 4;
    const int vcol = (tid & 15) * 4;

    float rm[4], ri[4];
    #pragma unroll
    for (int i=0;i<4;i++){
        int gr = bh*SEQ + m0 + lrow + i*32;
        rm[i] = g_rmax[gr];
        ri[i] = g_rinv[gr];
    }

    wmma::fragment<wmma::accumulator,16,16,8,float> acc[2][2];
    #pragma unroll
    for (int mi=0;mi<2;mi++)
        #pragma unroll
        for (int ni=0;ni<2;ni++)
            wmma::fill_fragment(acc[mi][ni], 0.0f);

    float4 pe[4], vv[2];
    int4 mk;
    #pragma unroll
    for (int i=0;i<4;i++)
        pe[i] = *(const float4*)(Arow + (size_t)(lrow + i*32)*SEQ + lcol);
    mk = *(const int4*)(maskb + lcol);
    #pragma unroll
    for (int i=0;i<2;i++)
        vv[i] = *(const float4*)(Vb + (size_t)(vrow + i*16)*HID + vcol);

    const int NKT = SEQ / TBK;  // 32
    for (int kt=0; kt<NKT; kt++){
        // transform current tile -> P, store to smem + write back to gmem
        #pragma unroll
        for (int i=0;i<4;i++){
            float4 e = pe[i];
            float4 p;
            float ex = (mk.x == 0) ? -1e10f : e.x;
            float ey = (mk.y == 0) ? -1e10f : e.y;
            float ez = (mk.z == 0) ? -1e10f : e.z;
            float ew = (mk.w == 0) ? -1e10f : e.w;
            p.x = __expf(ex - rm[i]) * ri[i];
            p.y = __expf(ey - rm[i]) * ri[i];
            p.z = __expf(ez - rm[i]) * ri[i];
            p.w = __expf(ew - rm[i]) * ri[i];
            *(float4*)(Ps + (lrow+i*32)*AVLDP + lcol) = p;
            *(float4*)(Arow + (size_t)(lrow + i*32)*SEQ + kt*TBK + lcol) = p;
        }
        #pragma unroll
        for (int i=0;i<2;i++)
            *(float4*)(Vs + (vrow+i*16)*AVLDV + vcol) = vv[i];
        __syncthreads();

        if (kt+1 < NKT){
            const int k0 = (kt+1)*TBK;
            #pragma unroll
            for (int i=0;i<4;i++)
                pe[i] = *(const float4*)(Arow + (size_t)(lrow + i*32)*SEQ + k0 + lcol);
            mk = *(const int4*)(maskb + k0 + lcol);
            #pragma unroll
            for (int i=0;i<2;i++)
                vv[i] = *(const float4*)(Vb + (size_t)(k0 + vrow + i*16)*HID + vcol);
        }

        #pragma unroll
        for (int kk=0; kk<TBK; kk+=8){
            wmma::fragment<wmma::matrix_a,16,16,8,wmma::precision::tf32,wmma::row_major> af[2];
            wmma::fragment<wmma::matrix_b,16,16,8,wmma::precision::tf32,wmma::row_major> bf[2];
            #pragma unroll
            for (int mi=0;mi<2;mi++){
                wmma::load_matrix_sync(af[mi], Ps + (wm*32+mi*16)*AVLDP + kk, AVLDP);
                #pragma unroll
                for (int t=0;t<af[mi].num_elements;t++)
                    af[mi].x[t] = wmma::__float_to_tf32(af[mi].x[t]);
            }
            #pragma unroll
            for (int ni=0;ni<2;ni++){
                wmma::load_matrix_sync(bf[ni], Vs + kk*AVLDV + wn*32 + ni*16, AVLDV);
                #pragma unroll
                for (int t=0;t<bf[ni].num_elements;t++)
                    bf[ni].x[t] = wmma::__float_to_tf32(bf[ni].x[t]);
            }
            #pragma unroll
            for (int mi=0;mi<2;mi++)
                #pragma unroll
                for (int ni=0;ni<2;ni++)
                    wmma::mma_sync(acc[mi][ni], af[mi], bf[ni], acc[mi][ni]);
        }
        __syncthreads();
    }

    #pragma unroll
    for (int mi=0;mi<2;mi++)
        #pragma unroll
        for (int ni=0;ni<2;ni++){
            float* dst = g_O + (size_t)(b*SEQ + m0 + wm*32 + mi*16)*HID
                             + h*HDIM + wn*32 + ni*16;
            wmma::store_matrix_sync(dst, acc[mi][ni], HID, wmma::mem_row_major);
        }
}

// ---------------------------------------------------------------------------
extern "C" void kernel_launch(void* const* d_in, const int* in_sizes, int n_in,
                              void* d_out, int out_size)
{
    const float* query = (const float*)d_in[0];
    const float* key   = (const float*)d_in[1];
    const float* value = (const float*)d_in[2];
    const float* Wq    = (const float*)d_in[3];
    const float* bq    = (const float*)d_in[4];
    const float* Wk    = (const float*)d_in[5];
    const float* bk    = (const float*)d_in[6];
    const float* Wv    = (const float*)d_in[7];
    const float* bv    = (const float*)d_in[8];
    const float* Wo    = (const float*)d_in[9];
    const float* bo    = (const float*)d_in[10];
    const int*   mask  = (const int*)d_in[11];

    float* out_x = (float*)d_out;
    float* attn  = out_x + (size_t)MROWS * HID;

    float *qb, *kb, *vb, *ob;
    cudaGetSymbolAddress((void**)&qb, g_Q);
    cudaGetSymbolAddress((void**)&kb, g_K);
    cudaGetSymbolAddress((void**)&vb, g_V);
    cudaGetSymbolAddress((void**)&ob, g_O);

    dim3 gproj(HID/TBN, MROWS/TBM);           // (8, 64)
    dim3 gbias(MROWS*HID/4/256);              // 8192
    dim3 genergy(SEQ/TBN, SEQ/TBM, BATCH*NHEADS);
    dim3 gav(SEQ/TBM, BATCH*NHEADS);

    // Q/K/V projections (Q pre-scaled by 1/sqrt(HDIM) = 1/8)
    proj_kernel<<<gproj, 256>>>(query, Wq, qb);
    bias_scale_kernel<<<gbias, 256>>>(qb, bq, 0.125f);
    proj_kernel<<<gproj, 256>>>(key, Wk, kb);
    bias_scale_kernel<<<gbias, 256>>>(kb, bk, 1.0f);
    proj_kernel<<<gproj, 256>>>(value, Wv, vb);
    bias_scale_kernel<<<gbias, 256>>>(vb, bv, 1.0f);

    // E = Q K^T (scale already folded into Q)
    energy_kernel<<<genergy, 256>>>(attn);

    // softmax row stats (mask applied here)
    stats_kernel<<<BHS/8, 256>>>(attn, mask);

    // P = softmax(E) written in place into attn; O = P @ V
    av_kernel<<<gav, 256>>>(attn, mask);

    // x = O @ Wo^T + bo
    proj_kernel<<<gproj, 256>>>(ob, Wo, out_x);
    bias_scale_kernel<<<gbias, 256>>>(out_x, bo, 1.0f);
}

// round 5
// speedup vs baseline: 1.0703x; 1.0703x over previous
#include <cuda_runtime.h>
#include <mma.h>

using namespace nvcuda;

#define HID    1024
#define NHEADS 16
#define HDIM   64
#define BATCH  8
#define SEQ    1024
#define MROWS  (BATCH*SEQ)        // 8192
#define BHS    (BATCH*NHEADS*SEQ) // 131072

// Scratch (device globals — no allocation allowed)
__device__ float g_Q[MROWS*HID];
__device__ float g_K[MROWS*HID];
__device__ float g_V[MROWS*HID];
__device__ float g_O[MROWS*HID];

// ---------------------------------------------------------------------------
// cp.async helpers
// ---------------------------------------------------------------------------
__device__ __forceinline__ void cp_async16(void* smem, const void* gmem){
    unsigned s = (unsigned)__cvta_generic_to_shared(smem);
    asm volatile("cp.async.cg.shared.global [%0], [%1], 16;\n" :: "r"(s), "l"(gmem));
}
#define CP_COMMIT()  asm volatile("cp.async.commit_group;\n" ::: "memory")
#define CP_WAIT0()   asm volatile("cp.async.wait_group 0;\n" ::: "memory")

// ===========================================================================
// Projection: C[M,1024] = (A[M,1024] @ W[1024,1024]^T + bias) * scale
// 128x128x32 tiles, tf32 wmma, cp.async double-buffered smem.
// ===========================================================================
#define TBM 128
#define TBN 128
#define TBK 32
#define LDT 36
#define PROJ_BUF (TBM*LDT)               // floats per A (or B) buffer
#define PROJ_SMEM_FLOATS (4*PROJ_BUF)    // As0,Bs0,As1,Bs1
#define PROJ_SMEM_BYTES (PROJ_SMEM_FLOATS*4)   // 73728
#define EPLD 132                          // epilogue smem leading dim

__global__ void __launch_bounds__(256,2)
proj_kernel(const float* __restrict__ A, const float* __restrict__ W,
            const float* __restrict__ bias, float scale, float* __restrict__ C)
{
    extern __shared__ float sm[];
    float* Asb[2] = { sm,              sm + 2*PROJ_BUF };
    float* Bsb[2] = { sm + PROJ_BUF,   sm + 3*PROJ_BUF };

    const int tid  = threadIdx.x;
    const int warp = tid >> 5;
    const int wm   = warp & 3;
    const int wn   = warp >> 2;
    const int m0   = blockIdx.y * TBM;
    const int n0   = blockIdx.x * TBN;

    wmma::fragment<wmma::accumulator,16,16,8,float> acc[2][4];
    #pragma unroll
    for (int mi=0;mi<2;mi++)
        #pragma unroll
        for (int ni=0;ni<4;ni++)
            wmma::fill_fragment(acc[mi][ni], 0.0f);

    // cp.async tile mapping: 128x32 floats, 4 float4 per thread
    const int lr  = tid >> 3;        // 0..31 (row within 32-row pass)
    const int lc4 = (tid & 7) * 4;   // 0,4,...,28

    // prefetch kt = 0
    {
        #pragma unroll
        for (int p=0;p<4;p++){
            int r = p*32 + lr;
            cp_async16(Asb[0] + r*LDT + lc4, A + (size_t)(m0 + r)*HID + lc4);
            cp_async16(Bsb[0] + r*LDT + lc4, W + (size_t)(n0 + r)*HID + lc4);
        }
        CP_COMMIT();
    }

    const int NKT = HID / TBK;  // 32
    for (int kt=0; kt<NKT; kt++){
        CP_WAIT0();
        __syncthreads();
        if (kt+1 < NKT){
            const int k0 = (kt+1)*TBK;
            float* Ad = Asb[(kt+1)&1];
            float* Bd = Bsb[(kt+1)&1];
            #pragma unroll
            for (int p=0;p<4;p++){
                int r = p*32 + lr;
                cp_async16(Ad + r*LDT + lc4, A + (size_t)(m0 + r)*HID + k0 + lc4);
                cp_async16(Bd + r*LDT + lc4, W + (size_t)(n0 + r)*HID + k0 + lc4);
            }
            CP_COMMIT();
        }
        const float* As = Asb[kt&1];
        const float* Bs = Bsb[kt&1];
        #pragma unroll
        for (int kk=0; kk<TBK; kk+=8){
            wmma::fragment<wmma::matrix_a,16,16,8,wmma::precision::tf32,wmma::row_major> af[2];
            wmma::fragment<wmma::matrix_b,16,16,8,wmma::precision::tf32,wmma::col_major> bf[4];
            #pragma unroll
            for (int mi=0;mi<2;mi++){
                wmma::load_matrix_sync(af[mi], As + (wm*32+mi*16)*LDT + kk, LDT);
                #pragma unroll
                for (int t=0;t<af[mi].num_elements;t++)
                    af[mi].x[t] = wmma::__float_to_tf32(af[mi].x[t]);
            }
            #pragma unroll
            for (int ni=0;ni<4;ni++){
                wmma::load_matrix_sync(bf[ni], Bs + (wn*64+ni*16)*LDT + kk, LDT);
                #pragma unroll
                for (int t=0;t<bf[ni].num_elements;t++)
                    bf[ni].x[t] = wmma::__float_to_tf32(bf[ni].x[t]);
            }
            #pragma unroll
            for (int mi=0;mi<2;mi++)
                #pragma unroll
                for (int ni=0;ni<4;ni++)
                    wmma::mma_sync(acc[mi][ni], af[mi], bf[ni], acc[mi][ni]);
        }
    }

    // Epilogue: stage tile in smem, add bias, scale, write coalesced
    __syncthreads();
    #pragma unroll
    for (int mi=0;mi<2;mi++)
        #pragma unroll
        for (int ni=0;ni<4;ni++)
            wmma::store_matrix_sync(sm + (wm*32+mi*16)*EPLD + wn*64 + ni*16,
                                    acc[mi][ni], EPLD, wmma::mem_row_major);
    __syncthreads();
    {
        const int er  = tid >> 5;         // 0..7
        const int ec4 = (tid & 31) * 4;   // 0..124
        float4 bb = *(const float4*)(bias + n0 + ec4);
        #pragma unroll
        for (int p=0;p<16;p++){
            int r = p*8 + er;
            float4 v = *(float4*)(sm + r*EPLD + ec4);
            v.x = (v.x + bb.x) * scale;
            v.y = (v.y + bb.y) * scale;
            v.z = (v.z + bb.z) * scale;
            v.w = (v.w + bb.w) * scale;
            *(float4*)(C + (size_t)(m0 + r)*HID + n0 + ec4) = v;
        }
    }
}

// ===========================================================================
// Fused attention: per block = 32 query rows of one (b,h).
//   Phase 1: E = Q Khᵀ (whole 32x1024 stripe resident in SMEM)
//   Phase 2: masked softmax in SMEM (exact rowmax), write P to gmem once
//   Phase 3: O = P Vh from SMEM
// ===========================================================================
#define STRIPE 32
#define CHUNK  128
#define LDE    1032
#define LDK    72
#define LDQ    72
#define FUSED_SMEM_FLOATS (STRIPE*LDE + STRIPE*LDQ + 2*CHUNK*LDK + SEQ)
#define FUSED_SMEM_BYTES  (FUSED_SMEM_FLOATS*4)   // 219136

__global__ void __launch_bounds__(256)
fused_attn_kernel(float* __restrict__ attn, const int* __restrict__ mask)
{
    extern __shared__ float smf[];
    float* Es  = smf;
    float* Qs  = Es + STRIPE*LDE;
    float* KV0 = Qs + STRIPE*LDQ;
    float* KV1 = KV0 + CHUNK*LDK;
    int*   Ms  = (int*)(KV1 + CHUNK*LDK);
    float* kvbuf[2] = { KV0, KV1 };

    const int tid  = threadIdx.x;
    const int warp = tid >> 5;
    const int lane = tid & 31;
    const int blk  = blockIdx.x;
    const int bh   = blk >> 5;          // 32 stripes per (b,h)
    const int strp = blk & 31;
    const int b    = bh >> 4;
    const int h    = bh & 15;
    const int m0   = strp * STRIPE;

    const float* Qb = g_Q + ((size_t)b*SEQ + m0)*HID + h*HDIM;
    const float* Kb = g_K + (size_t)b*SEQ*HID + h*HDIM;
    const float* Vb = g_V + (size_t)b*SEQ*HID + h*HDIM;

    // mask row -> smem
    for (int i = tid; i < SEQ/4; i += 256)
        *(int4*)(Ms + i*4) = *(const int4*)(mask + b*SEQ + i*4);

    // async-load Q stripe (32x64) + K chunk 0 (128x64)
    {
        const int r  = tid >> 4;          // 0..15
        const int c4 = (tid & 15) * 4;    // 0..60
        cp_async16(Qs + r*LDQ + c4,        Qb + (size_t)r*HID + c4);
        cp_async16(Qs + (r+16)*LDQ + c4,   Qb + (size_t)(r+16)*HID + c4);
        #pragma unroll
        for (int p=0;p<8;p++)
            cp_async16(KV0 + (p*16+r)*LDK + c4, Kb + (size_t)(p*16+r)*HID + c4);
        CP_COMMIT();
    }

    // -------- Phase 1: QK^T, E stripe into SMEM --------
    const int NC = SEQ / CHUNK;   // 8
    for (int c=0; c<NC; c++){
        CP_WAIT0();
        __syncthreads();
        if (c+1 < NC){
            const float* src = Kb + (size_t)(c+1)*CHUNK*HID;
            float* dst = kvbuf[(c+1)&1];
            const int r  = tid >> 4;
            const int c4 = (tid & 15) * 4;
            #pragma unroll
            for (int p=0;p<8;p++)
                cp_async16(dst + (p*16+r)*LDK + c4, src + (size_t)(p*16+r)*HID + c4);
            CP_COMMIT();
        }
        const float* Ks = kvbuf[c&1];
        wmma::fragment<wmma::accumulator,16,16,8,float> acc[2];
        wmma::fill_fragment(acc[0], 0.0f);
        wmma::fill_fragment(acc[1], 0.0f);
        #pragma unroll
        for (int k=0;k<HDIM;k+=8){
            wmma::fragment<wmma::matrix_a,16,16,8,wmma::precision::tf32,wmma::row_major> af[2];
            wmma::fragment<wmma::matrix_b,16,16,8,wmma::precision::tf32,wmma::col_major> bf;
            #pragma unroll
            for (int mi=0;mi<2;mi++){
                wmma::load_matrix_sync(af[mi], Qs + (mi*16)*LDQ + k, LDQ);
                #pragma unroll
                for (int t=0;t<af[mi].num_elements;t++)
                    af[mi].x[t] = wmma::__float_to_tf32(af[mi].x[t]);
            }
            wmma::load_matrix_sync(bf, Ks + (warp*16)*LDK + k, LDK);
            #pragma unroll
            for (int t=0;t<bf.num_elements;t++)
                bf.x[t] = wmma::__float_to_tf32(bf.x[t]);
            wmma::mma_sync(acc[0], af[0], bf, acc[0]);
            wmma::mma_sync(acc[1], af[1], bf, acc[1]);
        }
        #pragma unroll
        for (int mi=0;mi<2;mi++)
            wmma::store_matrix_sync(Es + (mi*16)*LDE + c*CHUNK + warp*16,
                                    acc[mi], LDE, wmma::mem_row_major);
    }

    // prefetch V chunk 0 while softmax runs (buf0 is free)
    {
        const int r  = tid >> 4;
        const int c4 = (tid & 15) * 4;
        #pragma unroll
        for (int p=0;p<8;p++)
            cp_async16(KV0 + (p*16+r)*LDK + c4, Vb + (size_t)(p*16+r)*HID + c4);
        CP_COMMIT();
    }
    __syncthreads();   // E stripe complete

    // -------- Phase 2: masked softmax (exact rowmax), write P once --------
    #pragma unroll
    for (int rr=0; rr<4; rr++){
        const int r = warp*4 + rr;
        float v[32];
        float mx = -1e30f;
        #pragma unroll
        for (int i=0;i<8;i++){
            float4 t  = *(float4*)(Es + r*LDE + i*128 + lane*4);
            int4   mk = *(const int4*)(Ms + i*128 + lane*4);
            t.x = (mk.x == 0) ? -1e10f : t.x;
            t.y = (mk.y == 0) ? -1e10f : t.y;
            t.z = (mk.z == 0) ? -1e10f : t.z;
            t.w = (mk.w == 0) ? -1e10f : t.w;
            v[i*4+0]=t.x; v[i*4+1]=t.y; v[i*4+2]=t.z; v[i*4+3]=t.w;
            mx = fmaxf(mx, fmaxf(fmaxf(t.x,t.y), fmaxf(t.z,t.w)));
        }
        #pragma unroll
        for (int o=16;o;o>>=1) mx = fmaxf(mx, __shfl_xor_sync(0xffffffffu, mx, o));
        float s = 0.0f;
        #pragma unroll
        for (int i=0;i<32;i++){ v[i] = __expf(v[i]-mx); s += v[i]; }
        #pragma unroll
        for (int o=16;o;o>>=1) s += __shfl_xor_sync(0xffffffffu, s, o);
        const float inv = 1.0f / s;
        float* arow = attn + ((size_t)bh*SEQ + m0 + r) * SEQ;
        #pragma unroll
        for (int i=0;i<8;i++){
            float4 p;
            p.x = v[i*4+0]*inv; p.y = v[i*4+1]*inv;
            p.z = v[i*4+2]*inv; p.w = v[i*4+3]*inv;
            *(float4*)(Es + r*LDE + i*128 + lane*4) = p;
            *(float4*)(arow + i*128 + lane*4) = p;
        }
    }
    __syncthreads();   // P stripe visible to all warps

    // -------- Phase 3: O = P V --------
    const int mi = warp & 1;
    const int ni = warp >> 1;
    wmma::fragment<wmma::accumulator,16,16,8,float> acco;
    wmma::fill_fragment(acco, 0.0f);

    for (int c=0; c<NC; c++){
        CP_WAIT0();
        __syncthreads();
        if (c+1 < NC){
            const float* src = Vb + (size_t)(c+1)*CHUNK*HID;
            float* dst = kvbuf[(c+1)&1];
            const int r  = tid >> 4;
            const int c4 = (tid & 15) * 4;
            #pragma unroll
            for (int p=0;p<8;p++)
                cp_async16(dst + (p*16+r)*LDK + c4, src + (size_t)(p*16+r)*HID + c4);
            CP_COMMIT();
        }
        const float* Vs = kvbuf[c&1];
        #pragma unroll
        for (int kk=0; kk<CHUNK; kk+=8){
            wmma::fragment<wmma::matrix_a,16,16,8,wmma::precision::tf32,wmma::row_major> af;
            wmma::fragment<wmma::matrix_b,16,16,8,wmma::precision::tf32,wmma::row_major> bf;
            wmma::load_matrix_sync(af, Es + (mi*16)*LDE + c*CHUNK + kk, LDE);
            #pragma unroll
            for (int t=0;t<af.num_elements;t++)
                af.x[t] = wmma::__float_to_tf32(af.x[t]);
            wmma::load_matrix_sync(bf, Vs + kk*LDK + ni*16, LDK);
            #pragma unroll
            for (int t=0;t<bf.num_elements;t++)
                bf.x[t] = wmma::__float_to_tf32(bf.x[t]);
            wmma::mma_sync(acco, af, bf, acco);
        }
    }

    wmma::store_matrix_sync(g_O + (size_t)(b*SEQ + m0 + mi*16)*HID + h*HDIM + ni*16,
                            acco, HID, wmma::mem_row_major);
}

// ---------------------------------------------------------------------------
extern "C" void kernel_launch(void* const* d_in, const int* in_sizes, int n_in,
                              void* d_out, int out_size)
{
    const float* query = (const float*)d_in[0];
    const float* key   = (const float*)d_in[1];
    const float* value = (const float*)d_in[2];
    const float* Wq    = (const float*)d_in[3];
    const float* bq    = (const float*)d_in[4];
    const float* Wk    = (const float*)d_in[5];
    const float* bk    = (const float*)d_in[6];
    const float* Wv    = (const float*)d_in[7];
    const float* bv    = (const float*)d_in[8];
    const float* Wo    = (const float*)d_in[9];
    const float* bo    = (const float*)d_in[10];
    const int*   mask  = (const int*)d_in[11];

    float* out_x = (float*)d_out;
    float* attn  = out_x + (size_t)MROWS * HID;

    float *qb, *kb, *vb, *ob;
    cudaGetSymbolAddress((void**)&qb, g_Q);
    cudaGetSymbolAddress((void**)&kb, g_K);
    cudaGetSymbolAddress((void**)&vb, g_V);
    cudaGetSymbolAddress((void**)&ob, g_O);

    static int attr_done = 0;
    if (!attr_done){
        cudaFuncSetAttribute(proj_kernel,
            cudaFuncAttributeMaxDynamicSharedMemorySize, PROJ_SMEM_BYTES);
        cudaFuncSetAttribute(fused_attn_kernel,
            cudaFuncAttributeMaxDynamicSharedMemorySize, FUSED_SMEM_BYTES);
        attr_done = 1;
    }

    dim3 gproj(HID/TBN, MROWS/TBM);   // (8, 64)

    // Projections with fused bias (+1/sqrt(64) folded into Q)
    proj_kernel<<<gproj, 256, PROJ_SMEM_BYTES>>>(query, Wq, bq, 0.125f, qb);
    proj_kernel<<<gproj, 256, PROJ_SMEM_BYTES>>>(key,   Wk, bk, 1.0f,  kb);
    proj_kernel<<<gproj, 256, PROJ_SMEM_BYTES>>>(value, Wv, bv, 1.0f,  vb);

    // Fused E = QK^T, softmax (writes attention to d_out), O = P V
    fused_attn_kernel<<<BHS/STRIPE, 256, FUSED_SMEM_BYTES>>>(attn, mask);

    // x = O Wo^T + bo
    proj_kernel<<<gproj, 256, PROJ_SMEM_BYTES>>>(ob, Wo, bo, 1.0f, out_x);
}

// round 7
// speedup vs baseline: 1.1202x; 1.0466x over previous
#include <cuda_runtime.h>
#include <mma.h>

using namespace nvcuda;

#define HID    1024
#define NHEADS 16
#define HDIM   64
#define BATCH  8
#define SEQ    1024
#define MROWS  (BATCH*SEQ)        // 8192
#define BHS    (BATCH*NHEADS*SEQ) // 131072

// Scratch (device globals — no allocation allowed)
__device__ float g_Q[MROWS*HID];
__device__ float g_K[MROWS*HID];
__device__ float g_V[MROWS*HID];
__device__ float g_O[MROWS*HID];

// ---------------------------------------------------------------------------
// cp.async helpers
// ---------------------------------------------------------------------------
__device__ __forceinline__ void cp_async16(void* smem, const void* gmem){
    unsigned s = (unsigned)__cvta_generic_to_shared(smem);
    asm volatile("cp.async.cg.shared.global [%0], [%1], 16;\n" :: "r"(s), "l"(gmem));
}
#define CP_COMMIT()  asm volatile("cp.async.commit_group;\n" ::: "memory")
#define CP_WAIT0()   asm volatile("cp.async.wait_group 0;\n" ::: "memory")

// ===========================================================================
// Projection body: C[M,1024] = (A[M,1024] @ W[1024,1024]^T + bias) * scale
// 128x128x32 tiles, tf32 wmma, cp.async double-buffered smem.
// ===========================================================================
#define TBM 128
#define TBN 128
#define TBK 32
#define LDT 36
#define PROJ_BUF (TBM*LDT)
#define PROJ_SMEM_FLOATS (4*PROJ_BUF)
#define PROJ_SMEM_BYTES (PROJ_SMEM_FLOATS*4)   // 73728
#define EPLD 132

__device__ __forceinline__
void proj_body(const float* __restrict__ A, const float* __restrict__ W,
               const float* __restrict__ bias, float scale, float* __restrict__ C,
               float* sm)
{
    float* Asb[2] = { sm,              sm + 2*PROJ_BUF };
    float* Bsb[2] = { sm + PROJ_BUF,   sm + 3*PROJ_BUF };

    const int tid  = threadIdx.x;
    const int warp = tid >> 5;
    const int wm   = warp & 3;
    const int wn   = warp >> 2;
    const int m0   = blockIdx.y * TBM;
    const int n0   = blockIdx.x * TBN;

    wmma::fragment<wmma::accumulator,16,16,8,float> acc[2][4];
    #pragma unroll
    for (int mi=0;mi<2;mi++)
        #pragma unroll
        for (int ni=0;ni<4;ni++)
            wmma::fill_fragment(acc[mi][ni], 0.0f);

    const int lr  = tid >> 3;
    const int lc4 = (tid & 7) * 4;

    {
        #pragma unroll
        for (int p=0;p<4;p++){
            int r = p*32 + lr;
            cp_async16(Asb[0] + r*LDT + lc4, A + (size_t)(m0 + r)*HID + lc4);
            cp_async16(Bsb[0] + r*LDT + lc4, W + (size_t)(n0 + r)*HID + lc4);
        }
        CP_COMMIT();
    }

    const int NKT = HID / TBK;  // 32
    for (int kt=0; kt<NKT; kt++){
        CP_WAIT0();
        __syncthreads();
        if (kt+1 < NKT){
            const int k0 = (kt+1)*TBK;
            float* Ad = Asb[(kt+1)&1];
            float* Bd = Bsb[(kt+1)&1];
            #pragma unroll
            for (int p=0;p<4;p++){
                int r = p*32 + lr;
                cp_async16(Ad + r*LDT + lc4, A + (size_t)(m0 + r)*HID + k0 + lc4);
                cp_async16(Bd + r*LDT + lc4, W + (size_t)(n0 + r)*HID + k0 + lc4);
            }
            CP_COMMIT();
        }
        const float* As = Asb[kt&1];
        const float* Bs = Bsb[kt&1];
        #pragma unroll
        for (int kk=0; kk<TBK; kk+=8){
            wmma::fragment<wmma::matrix_a,16,16,8,wmma::precision::tf32,wmma::row_major> af[2];
            wmma::fragment<wmma::matrix_b,16,16,8,wmma::precision::tf32,wmma::col_major> bf[4];
            #pragma unroll
            for (int mi=0;mi<2;mi++){
                wmma::load_matrix_sync(af[mi], As + (wm*32+mi*16)*LDT + kk, LDT);
                #pragma unroll
                for (int t=0;t<af[mi].num_elements;t++)
                    af[mi].x[t] = wmma::__float_to_tf32(af[mi].x[t]);
            }
            #pragma unroll
            for (int ni=0;ni<4;ni++){
                wmma::load_matrix_sync(bf[ni], Bs + (wn*64+ni*16)*LDT + kk, LDT);
                #pragma unroll
                for (int t=0;t<bf[ni].num_elements;t++)
                    bf[ni].x[t] = wmma::__float_to_tf32(bf[ni].x[t]);
            }
            #pragma unroll
            for (int mi=0;mi<2;mi++)
                #pragma unroll
                for (int ni=0;ni<4;ni++)
                    wmma::mma_sync(acc[mi][ni], af[mi], bf[ni], acc[mi][ni]);
        }
    }

    __syncthreads();
    #pragma unroll
    for (int mi=0;mi<2;mi++)
        #pragma unroll
        for (int ni=0;ni<4;ni++)
            wmma::store_matrix_sync(sm + (wm*32+mi*16)*EPLD + wn*64 + ni*16,
                                    acc[mi][ni], EPLD, wmma::mem_row_major);
    __syncthreads();
    {
        const int er  = tid >> 5;
        const int ec4 = (tid & 31) * 4;
        float4 bb = *(const float4*)(bias + n0 + ec4);
        #pragma unroll
        for (int p=0;p<16;p++){
            int r = p*8 + er;
            float4 v = *(float4*)(sm + r*EPLD + ec4);
            v.x = (v.x + bb.x) * scale;
            v.y = (v.y + bb.y) * scale;
            v.z = (v.z + bb.z) * scale;
            v.w = (v.w + bb.w) * scale;
            *(float4*)(C + (size_t)(m0 + r)*HID + n0 + ec4) = v;
        }
    }
}

// Merged Q/K/V projection: blockIdx.z selects which projection
__global__ void __launch_bounds__(256,2)
qkv_proj_kernel(const float* __restrict__ q, const float* __restrict__ k,
                const float* __restrict__ v,
                const float* __restrict__ Wq, const float* __restrict__ Wk,
                const float* __restrict__ Wv,
                const float* __restrict__ bq, const float* __restrict__ bk,
                const float* __restrict__ bv,
                float* __restrict__ qo, float* __restrict__ ko, float* __restrict__ vo)
{
    extern __shared__ float sm[];
    const int z = blockIdx.z;
    const float* A    = (z==0) ? q  : (z==1) ? k  : v;
    const float* W    = (z==0) ? Wq : (z==1) ? Wk : Wv;
    const float* bias = (z==0) ? bq : (z==1) ? bk : bv;
    float*       C    = (z==0) ? qo : (z==1) ? ko : vo;
    const float scale = (z==0) ? 0.125f : 1.0f;
    proj_body(A, W, bias, scale, C, sm);
}

__global__ void __launch_bounds__(256,2)
proj_kernel(const float* __restrict__ A, const float* __restrict__ W,
            const float* __restrict__ bias, float scale, float* __restrict__ C)
{
    extern __shared__ float sm[];
    proj_body(A, W, bias, scale, C, sm);
}

// ===========================================================================
// Fused attention: per block = 32 query rows of one (b,h). 512 threads,
// two warp-groups of 8 warps with private double-buffered 64-col K/V chunks.
//   Phase 1: E = Q Kh^T  (group g handles chunks c ≡ g mod 2)
//   Phase 2: masked softmax in SMEM (exact rowmax), write P to gmem once
//   Phase 3: O = P Vh    (group g handles k in [g*512, g*512+512)), smem-reduce
// FIX vs R6: Q stripe is loaded by threads of BOTH groups via cp.async, so its
// completion must be established by CP_WAIT0 on ALL threads followed by a FULL
// __syncthreads() before any warp reads Qs. Group-scoped waits are not enough.
// ===========================================================================
#define STRIPE 32
#define CH     64
#define NCHUNK (SEQ/CH)           // 16
#define LDE    1032
#define LDK    72
#define LDQ    72
#define CHBUF  (CH*LDK)
#define FUSED_SMEM_FLOATS (STRIPE*LDE + STRIPE*LDQ + 4*CHBUF + SEQ)
#define FUSED_SMEM_BYTES  (FUSED_SMEM_FLOATS*4)   // 219136

__device__ __forceinline__ void bar_group(int grp){
    asm volatile("bar.sync %0, 256;" :: "r"(grp+1) : "memory");
}

__global__ void __launch_bounds__(512,1)
fused_attn_kernel(float* __restrict__ attn, const int* __restrict__ mask)
{
    extern __shared__ float smf[];
    float* Es  = smf;                      // 32 x 1032
    float* Qs  = Es + STRIPE*LDE;          // 32 x 72 (reused as O-reduce buffer)
    float* KVB = Qs + STRIPE*LDQ;          // 4 chunk buffers of 64 x 72
    int*   Ms  = (int*)(KVB + 4*CHBUF);    // 1024 ints

    const int tid   = threadIdx.x;
    const int warp  = tid >> 5;
    const int lane  = tid & 31;
    const int grp   = tid >> 8;            // 0 or 1
    const int gwarp = warp & 7;
    const int gtid  = tid & 255;

    const int blk  = blockIdx.x;
    const int bh   = blk >> 5;
    const int strp = blk & 31;
    const int b    = bh >> 4;
    const int h    = bh & 15;
    const int m0   = strp * STRIPE;

    const float* Qb = g_Q + ((size_t)b*SEQ + m0)*HID + h*HDIM;
    const float* Kb = g_K + (size_t)b*SEQ*HID + h*HDIM;
    const float* Vb = g_V + (size_t)b*SEQ*HID + h*HDIM;

    float* mybuf[2] = { KVB + (grp*2)*CHBUF, KVB + (grp*2+1)*CHBUF };

    // mask row -> smem
    if (tid < 256)
        *(int4*)(Ms + tid*4) = *(const int4*)(mask + b*SEQ + tid*4);

    // Q stripe: 32x64 floats, one float4 per thread (both groups contribute!)
    {
        const int r  = tid >> 4;
        const int c4 = (tid & 15) * 4;
        cp_async16(Qs + r*LDQ + c4, Qb + (size_t)r*HID + c4);
    }
    // group g prefetches K chunk c0 = g into its buf0
    {
        const int r  = gtid >> 4;
        const int c4 = (gtid & 15) * 4;
        const float* src = Kb + (size_t)(grp*CH)*HID;
        #pragma unroll
        for (int p=0;p<4;p++)
            cp_async16(mybuf[0] + (p*16+r)*LDK + c4, src + (size_t)(p*16+r)*HID + c4);
        CP_COMMIT();
    }
    // FIX: every thread waits its own cp.asyncs, then FULL barrier.
    // Makes the cross-group-loaded Q stripe (and mask, K0) visible to all.
    CP_WAIT0();
    __syncthreads();

    // -------- Phase 1: QK^T --------
    const int wm = gwarp & 1;    // m tile (16 rows)
    const int wn = gwarp >> 1;   // n tile (16 of 64 cols)
    for (int ci=0; ci<NCHUNK/2; ci++){
        const int c = 2*ci + grp;
        CP_WAIT0();               // waits prefetch issued at ci-1 (no-op at ci=0)
        bar_group(grp);
        if (ci+1 < NCHUNK/2){
            const int cn = c + 2;
            const float* src = Kb + (size_t)(cn*CH)*HID;
            float* dst = mybuf[(ci+1)&1];
            const int r  = gtid >> 4;
            const int c4 = (gtid & 15) * 4;
            #pragma unroll
            for (int p=0;p<4;p++)
                cp_async16(dst + (p*16+r)*LDK + c4, src + (size_t)(p*16+r)*HID + c4);
            CP_COMMIT();
        }
        const float* Ks = mybuf[ci&1];
        wmma::fragment<wmma::accumulator,16,16,8,float> a0, a1;
        wmma::fill_fragment(a0, 0.0f);
        wmma::fill_fragment(a1, 0.0f);
        #pragma unroll
        for (int k=0;k<HDIM;k+=16){
            wmma::fragment<wmma::matrix_a,16,16,8,wmma::precision::tf32,wmma::row_major> af0, af1;
            wmma::fragment<wmma::matrix_b,16,16,8,wmma::precision::tf32,wmma::col_major> bf0, bf1;
            wmma::load_matrix_sync(af0, Qs + (wm*16)*LDQ + k, LDQ);
            wmma::load_matrix_sync(af1, Qs + (wm*16)*LDQ + k + 8, LDQ);
            wmma::load_matrix_sync(bf0, Ks + (wn*16)*LDK + k, LDK);
            wmma::load_matrix_sync(bf1, Ks + (wn*16)*LDK + k + 8, LDK);
            #pragma unroll
            for (int t=0;t<af0.num_elements;t++){
                af0.x[t] = wmma::__float_to_tf32(af0.x[t]);
                af1.x[t] = wmma::__float_to_tf32(af1.x[t]);
            }
            #pragma unroll
            for (int t=0;t<bf0.num_elements;t++){
                bf0.x[t] = wmma::__float_to_tf32(bf0.x[t]);
                bf1.x[t] = wmma::__float_to_tf32(bf1.x[t]);
            }
            wmma::mma_sync(a0, af0, bf0, a0);
            wmma::mma_sync(a1, af1, bf1, a1);
        }
        #pragma unroll
        for (int t=0;t<a0.num_elements;t++) a0.x[t] += a1.x[t];
        wmma::store_matrix_sync(Es + (wm*16)*LDE + c*CH + wn*16, a0, LDE,
                                wmma::mem_row_major);
    }

    // prefetch first V chunk for this group into its buf0 (group-private)
    {
        const float* src = Vb + (size_t)(grp*8*CH)*HID;
        const int r  = gtid >> 4;
        const int c4 = (gtid & 15) * 4;
        #pragma unroll
        for (int p=0;p<4;p++)
            cp_async16(mybuf[0] + (p*16+r)*LDK + c4, src + (size_t)(p*16+r)*HID + c4);
        CP_COMMIT();
    }
    __syncthreads();   // E stripe complete (regular smem stores — barrier suffices)

    // -------- Phase 2: masked softmax, write P once (2 rows per warp) --------
    #pragma unroll
    for (int rr=0; rr<2; rr++){
        const int r = warp*2 + rr;
        float v[32];
        float mx = -1e30f;
        #pragma unroll
        for (int i=0;i<8;i++){
            float4 t  = *(float4*)(Es + r*LDE + i*128 + lane*4);
            int4   mk = *(const int4*)(Ms + i*128 + lane*4);
            t.x = (mk.x == 0) ? -1e10f : t.x;
            t.y = (mk.y == 0) ? -1e10f : t.y;
            t.z = (mk.z == 0) ? -1e10f : t.z;
            t.w = (mk.w == 0) ? -1e10f : t.w;
            v[i*4+0]=t.x; v[i*4+1]=t.y; v[i*4+2]=t.z; v[i*4+3]=t.w;
            mx = fmaxf(mx, fmaxf(fmaxf(t.x,t.y), fmaxf(t.z,t.w)));
        }
        #pragma unroll
        for (int o=16;o;o>>=1) mx = fmaxf(mx, __shfl_xor_sync(0xffffffffu, mx, o));
        float s = 0.0f;
        #pragma unroll
        for (int i=0;i<32;i++){ v[i] = __expf(v[i]-mx); s += v[i]; }
        #pragma unroll
        for (int o=16;o;o>>=1) s += __shfl_xor_sync(0xffffffffu, s, o);
        const float inv = 1.0f / s;
        float* arow = attn + ((size_t)bh*SEQ + m0 + r) * SEQ;
        #pragma unroll
        for (int i=0;i<8;i++){
            float4 p;
            p.x = v[i*4+0]*inv; p.y = v[i*4+1]*inv;
            p.z = v[i*4+2]*inv; p.w = v[i*4+3]*inv;
            *(float4*)(Es + r*LDE + i*128 + lane*4) = p;
            *(float4*)(arow + i*128 + lane*4) = p;
        }
    }
    __syncthreads();   // P stripe visible to all warps

    // -------- Phase 3: O = P V, k split across groups --------
    wmma::fragment<wmma::accumulator,16,16,8,float> o0, o1;
    wmma::fill_fragment(o0, 0.0f);
    wmma::fill_fragment(o1, 0.0f);
    const int pn = gwarp >> 1;   // 4 n tiles of 16 (HDIM=64)

    for (int ci=0; ci<8; ci++){
        CP_WAIT0();
        bar_group(grp);
        if (ci+1 < 8){
            const float* src = Vb + (size_t)(grp*8*CH + (ci+1)*CH)*HID;
            float* dst = mybuf[(ci+1)&1];
            const int r  = gtid >> 4;
            const int c4 = (gtid & 15) * 4;
            #pragma unroll
            for (int p=0;p<4;p++)
                cp_async16(dst + (p*16+r)*LDK + c4, src + (size_t)(p*16+r)*HID + c4);
            CP_COMMIT();
        }
        const float* Vs = mybuf[ci&1];
        const int kbase = grp*8*CH + ci*CH;
        #pragma unroll
        for (int kk=0; kk<CH; kk+=16){
            wmma::fragment<wmma::matrix_a,16,16,8,wmma::precision::tf32,wmma::row_major> af0, af1;
            wmma::fragment<wmma::matrix_b,16,16,8,wmma::precision::tf32,wmma::row_major> bf0, bf1;
            wmma::load_matrix_sync(af0, Es + (wm*16)*LDE + kbase + kk, LDE);
            wmma::load_matrix_sync(af1, Es + (wm*16)*LDE + kbase + kk + 8, LDE);
            wmma::load_matrix_sync(bf0, Vs + kk*LDK + pn*16, LDK);
            wmma::load_matrix_sync(bf1, Vs + (kk+8)*LDK + pn*16, LDK);
            #pragma unroll
            for (int t=0;t<af0.num_elements;t++){
                af0.x[t] = wmma::__float_to_tf32(af0.x[t]);
                af1.x[t] = wmma::__float_to_tf32(af1.x[t]);
            }
            #pragma unroll
            for (int t=0;t<bf0.num_elements;t++){
                bf0.x[t] = wmma::__float_to_tf32(bf0.x[t]);
                bf1.x[t] = wmma::__float_to_tf32(bf1.x[t]);
            }
            wmma::mma_sync(o0, af0, bf0, o0);
            wmma::mma_sync(o1, af1, bf1, o1);
        }
    }
    #pragma unroll
    for (int t=0;t<o0.num_elements;t++) o0.x[t] += o1.x[t];

    // cross-group reduction via Qs (free after phase 1): group 1 stores,
    // full barrier, group 0 adds and writes final O. Regular smem stores.
    if (grp == 1)
        wmma::store_matrix_sync(Qs + (wm*16)*LDQ + pn*16, o0, LDQ,
                                wmma::mem_row_major);
    __syncthreads();
    if (grp == 0){
        wmma::fragment<wmma::accumulator,16,16,8,float> part;
        wmma::load_matrix_sync(part, Qs + (wm*16)*LDQ + pn*16, LDQ,
                               wmma::mem_row_major);
        #pragma unroll
        for (int t=0;t<o0.num_elements;t++) o0.x[t] += part.x[t];
        wmma::store_matrix_sync(g_O + (size_t)(b*SEQ + m0 + wm*16)*HID
                                    + h*HDIM + pn*16,
                                o0, HID, wmma::mem_row_major);
    }
}

// ---------------------------------------------------------------------------
extern "C" void kernel_launch(void* const* d_in, const int* in_sizes, int n_in,
                              void* d_out, int out_size)
{
    const float* query = (const float*)d_in[0];
    const float* key   = (const float*)d_in[1];
    const float* value = (const float*)d_in[2];
    const float* Wq    = (const float*)d_in[3];
    const float* bq    = (const float*)d_in[4];
    const float* Wk    = (const float*)d_in[5];
    const float* bk    = (const float*)d_in[6];
    const float* Wv    = (const float*)d_in[7];
    const float* bv    = (const float*)d_in[8];
    const float* Wo    = (const float*)d_in[9];
    const float* bo    = (const float*)d_in[10];
    const int*   mask  = (const int*)d_in[11];

    float* out_x = (float*)d_out;
    float* attn  = out_x + (size_t)MROWS * HID;

    float *qb, *kb, *vb, *ob;
    cudaGetSymbolAddress((void**)&qb, g_Q);
    cudaGetSymbolAddress((void**)&kb, g_K);
    cudaGetSymbolAddress((void**)&vb, g_V);
    cudaGetSymbolAddress((void**)&ob, g_O);

    static int attr_done = 0;
    if (!attr_done){
        cudaFuncSetAttribute(qkv_proj_kernel,
            cudaFuncAttributeMaxDynamicSharedMemorySize, PROJ_SMEM_BYTES);
        cudaFuncSetAttribute(proj_kernel,
            cudaFuncAttributeMaxDynamicSharedMemorySize, PROJ_SMEM_BYTES);
        cudaFuncSetAttribute(fused_attn_kernel,
            cudaFuncAttributeMaxDynamicSharedMemorySize, FUSED_SMEM_BYTES);
        attr_done = 1;
    }

    dim3 gqkv(HID/TBN, MROWS/TBM, 3);   // (8, 64, 3)
    dim3 gproj(HID/TBN, MROWS/TBM);     // (8, 64)

    // Q/K/V projections in one launch (1/sqrt(64) folded into Q)
    qkv_proj_kernel<<<gqkv, 256, PROJ_SMEM_BYTES>>>(
        query, key, value, Wq, Wk, Wv, bq, bk, bv, qb, kb, vb);

    // Fused E = QK^T, softmax (writes attention to d_out), O = P V
    fused_attn_kernel<<<BHS/STRIPE, 512, FUSED_SMEM_BYTES>>>(attn, mask);

    // x = O Wo^T + bo
    proj_kernel<<<gproj, 256, PROJ_SMEM_BYTES>>>(ob, Wo, bo, 1.0f, out_x);
}